// round 1
// baseline (speedup 1.0000x reference)
#include <cuda_runtime.h>
#include <math.h>

#define NUM_EXPERTS 16
#define FREQ_BINS   2097152
#define ROW_V       (FREQ_BINS / 4)   // 524288 float4 per row = 2^19

__device__ int g_starts[NUM_EXPERTS];
__device__ int g_ends[NUM_EXPERTS];

// Tiny scalar prologue: sigmoid(15 params) in double (XLA expands logistic as
// 0.5 + 0.5*tanh(0.5x)), cast to f32, sort with the {0,1} endpoints, scale by
// (FREQ_BINS-1) in f32 and truncate — mirroring the reference's rounding path
// exactly so bin boundaries match to the element.
__global__ void prep_kernel(const float* __restrict__ bp) {
    float b[NUM_EXPERTS + 1];
    b[0] = 0.0f;
    b[NUM_EXPERTS] = 1.0f;
#pragma unroll
    for (int i = 0; i < NUM_EXPERTS - 1; i++) {
        double x = (double)bp[i];
        double s = 0.5 + 0.5 * tanh(0.5 * x);
        b[i + 1] = (float)s;
    }
    // insertion sort all 17 (cheap; sigmoid is monotone but match jnp.sort anyway)
    for (int i = 1; i <= NUM_EXPERTS; i++) {
        float key = b[i];
        int j = i - 1;
        while (j >= 0 && b[j] > key) { b[j + 1] = b[j]; j--; }
        b[j + 1] = key;
    }
#pragma unroll
    for (int e = 0; e < NUM_EXPERTS; e++) {
        g_starts[e] = (int)(b[e] * 2097151.0f);                 // f32 mul, trunc
        g_ends[e]   = (e < NUM_EXPERTS - 1)
                        ? (int)(b[e + 1] * 2097151.0f)
                        : FREQ_BINS;
    }
}

// Pure write-stream kernel: one float4 (STG.128) per iteration, grid-stride.
// v >> 19 = expert row, (v & (2^19-1))*4 = position. Two int compares + SELs
// per lane; DRAM-write bound by construction.
__global__ void __launch_bounds__(256) masks_kernel(float4* __restrict__ out) {
    const unsigned total  = NUM_EXPERTS * ROW_V;   // 8388608
    unsigned v      = blockIdx.x * blockDim.x + threadIdx.x;
    unsigned stride = gridDim.x * blockDim.x;

    for (; v < total; v += stride) {
        unsigned e = v >> 19;
        int p = (int)((v & (ROW_V - 1)) << 2);
        int s  = g_starts[e];
        int en = g_ends[e];
        float4 f;
        f.x = (p     >= s && p     < en) ? 1.0f : 0.0f;
        f.y = (p + 1 >= s && p + 1 < en) ? 1.0f : 0.0f;
        f.z = (p + 2 >= s && p + 2 < en) ? 1.0f : 0.0f;
        f.w = (p + 3 >= s && p + 3 < en) ? 1.0f : 0.0f;
        out[v] = f;
    }
}

extern "C" void kernel_launch(void* const* d_in, const int* in_sizes, int n_in,
                              void* d_out, int out_size) {
    const float* bound_params = (const float*)d_in[0];
    float4* out = (float4*)d_out;

    prep_kernel<<<1, 1>>>(bound_params);

    // 4096 blocks x 256 threads = 1M threads, 8 float4 stores each (grid-stride).
    masks_kernel<<<4096, 256>>>(out);
}

// round 2
// speedup vs baseline: 1.0747x; 1.0747x over previous
#include <cuda_runtime.h>
#include <math.h>

#define NUM_EXPERTS 16
#define FREQ_BINS   2097152
#define ROW_V       (FREQ_BINS / 4)     // 524288 float4 per row = 2^19
#define ITERS       8                   // float4 stores per thread
#define TPB         256
#define BLOCKS_X    (ROW_V / (TPB * ITERS))   // 256

// Single fused kernel. Every block redundantly computes the bounds for its own
// expert row (blockIdx.y): 15 parallel double-precision sigmoids (XLA logistic
// = 0.5 + 0.5*tanh(0.5x), cast to f32 — identical math to the passing R1
// kernel, rel_err was 0.0), a 17-element insertion sort on one thread, then a
// pure STG.128 write stream. No second kernel, no inter-kernel dependency.
__global__ void __launch_bounds__(TPB) freq_bands_fused(
    const float* __restrict__ bp, float4* __restrict__ out)
{
    __shared__ float sb[NUM_EXPERTS + 1];
    __shared__ int s_bounds[2];

    const int tid = threadIdx.x;
    const int e   = blockIdx.y;

    // 15 threads compute sigmoids in parallel (one double tanh each).
    if (tid < NUM_EXPERTS - 1) {
        double x = (double)bp[tid];
        sb[tid + 1] = (float)(0.5 + 0.5 * tanh(0.5 * x));
    } else if (tid == NUM_EXPERTS - 1) {
        sb[0] = 0.0f;
    } else if (tid == NUM_EXPERTS) {
        sb[NUM_EXPERTS] = 1.0f;
    }
    __syncthreads();

    // One thread sorts and derives this block's [start, end).
    if (tid == 0) {
        float b[NUM_EXPERTS + 1];
#pragma unroll
        for (int i = 0; i <= NUM_EXPERTS; i++) b[i] = sb[i];
        for (int i = 1; i <= NUM_EXPERTS; i++) {   // insertion sort, 17 elems
            float key = b[i];
            int j = i - 1;
            while (j >= 0 && b[j] > key) { b[j + 1] = b[j]; j--; }
            b[j + 1] = key;
        }
        int s  = (int)(b[e] * 2097151.0f);         // f32 mul + trunc (matches ref)
        int en = (e < NUM_EXPERTS - 1) ? (int)(b[e + 1] * 2097151.0f)
                                       : FREQ_BINS;
        s_bounds[0] = s;
        s_bounds[1] = en;
    }
    __syncthreads();

    const int s   = s_bounds[0];
    const unsigned len = (unsigned)(s_bounds[1] - s_bounds[0]);

    // Write stream: element in range iff (unsigned)(p - s) < len  (1 cmp/elem).
    float4* row = out + (size_t)e * ROW_V;
    const unsigned base = blockIdx.x * (TPB * ITERS) + tid;

#pragma unroll
    for (int i = 0; i < ITERS; i++) {
        unsigned v = base + i * TPB;           // float4 index within the row
        int p = (int)(v << 2) - s;             // element offset relative to start
        float4 f;
        f.x = ((unsigned)(p    ) < len) ? 1.0f : 0.0f;
        f.y = ((unsigned)(p + 1) < len) ? 1.0f : 0.0f;
        f.z = ((unsigned)(p + 2) < len) ? 1.0f : 0.0f;
        f.w = ((unsigned)(p + 3) < len) ? 1.0f : 0.0f;
        row[v] = f;
    }
}

extern "C" void kernel_launch(void* const* d_in, const int* in_sizes, int n_in,
                              void* d_out, int out_size) {
    const float* bound_params = (const float*)d_in[0];
    float4* out = (float4*)d_out;

    dim3 grid(BLOCKS_X, NUM_EXPERTS);   // (256, 16) blocks x 256 threads
    freq_bands_fused<<<grid, TPB>>>(bound_params, out);
}

// round 3
// speedup vs baseline: 1.3318x; 1.2393x over previous
#include <cuda_runtime.h>
#include <math.h>

#define NUM_EXPERTS 16
#define FREQ_BINS   2097152
#define ROW_V       (FREQ_BINS / 4)          // 524288 float4 per row = 2^19
#define TPB         256
#define ITERS       8
#define BLOCKS_X    (ROW_V / (TPB * ITERS))  // 256

__device__ int g_bounds[2 * NUM_EXPERTS];    // [start_e, end_e] pairs

// Prep: ONE warp. 15 lanes compute the double-precision sigmoids in parallel
// (XLA logistic = 0.5 + 0.5*tanh(0.5x), cast to f32 — byte-identical to the
// R1/R2 prologue that measured rel_err=0.0). Lane 0 then sorts 17 values and
// emits all 16 [start,end) pairs.
__global__ void prep_kernel(const float* __restrict__ bp) {
    __shared__ float sb[NUM_EXPERTS + 1];
    const int tid = threadIdx.x;

    if (tid < NUM_EXPERTS - 1) {
        double x = (double)bp[tid];
        sb[tid + 1] = (float)(0.5 + 0.5 * tanh(0.5 * x));
    }
    if (tid == NUM_EXPERTS - 1) sb[0] = 0.0f;
    if (tid == NUM_EXPERTS)     sb[NUM_EXPERTS] = 1.0f;
    __syncwarp();

    if (tid == 0) {
        float b[NUM_EXPERTS + 1];
#pragma unroll
        for (int i = 0; i <= NUM_EXPERTS; i++) b[i] = sb[i];
        for (int i = 1; i <= NUM_EXPERTS; i++) {   // insertion sort, 17 elems
            float key = b[i];
            int j = i - 1;
            while (j >= 0 && b[j] > key) { b[j + 1] = b[j]; j--; }
            b[j + 1] = key;
        }
#pragma unroll
        for (int e = 0; e < NUM_EXPERTS; e++) {
            g_bounds[2 * e]     = (int)(b[e] * 2097151.0f);   // f32 mul + trunc
            g_bounds[2 * e + 1] = (e < NUM_EXPERTS - 1)
                                    ? (int)(b[e + 1] * 2097151.0f)
                                    : FREQ_BINS;
        }
    }
}

// Pure STG.128 write stream. blockIdx.y = expert row, so bounds are
// block-uniform; in-range test is one unsigned compare per element.
// cudaGridDependencySynchronize() lets this grid pre-launch under PDL and
// park until prep's writes are visible.
__global__ void __launch_bounds__(TPB) masks_kernel(float4* __restrict__ out) {
#if __CUDA_ARCH__ >= 900
    cudaGridDependencySynchronize();
#endif
    const int e  = blockIdx.y;
    const int s  = g_bounds[2 * e];
    const unsigned len = (unsigned)(g_bounds[2 * e + 1] - s);

    float4* row = out + (size_t)e * ROW_V;
    const unsigned base = blockIdx.x * (TPB * ITERS) + threadIdx.x;

#pragma unroll
    for (int i = 0; i < ITERS; i++) {
        unsigned v = base + i * TPB;       // float4 index within the row
        int p = (int)(v << 2) - s;         // element offset relative to start
        float4 f;
        f.x = ((unsigned)(p    ) < len) ? 1.0f : 0.0f;
        f.y = ((unsigned)(p + 1) < len) ? 1.0f : 0.0f;
        f.z = ((unsigned)(p + 2) < len) ? 1.0f : 0.0f;
        f.w = ((unsigned)(p + 3) < len) ? 1.0f : 0.0f;
        row[v] = f;
    }
}

extern "C" void kernel_launch(void* const* d_in, const int* in_sizes, int n_in,
                              void* d_out, int out_size) {
    const float* bound_params = (const float*)d_in[0];
    float4* out = (float4*)d_out;

    prep_kernel<<<1, 32>>>(bound_params);

    // PDL: pre-launch the store grid; it parks at cudaGridDependencySynchronize
    // until prep completes (no trigger in prep -> conservative full-completion
    // semantics, memory guaranteed visible).
    cudaLaunchConfig_t cfg = {};
    cfg.gridDim  = dim3(BLOCKS_X, NUM_EXPERTS);
    cfg.blockDim = dim3(TPB);
    cudaLaunchAttribute attr[1];
    attr[0].id = cudaLaunchAttributeProgrammaticStreamSerialization;
    attr[0].val.programmaticStreamSerializationAllowed = 1;
    cfg.attrs    = attr;
    cfg.numAttrs = 1;
    cudaLaunchKernelEx(&cfg, masks_kernel, out);
}

// round 4
// speedup vs baseline: 1.3932x; 1.0460x over previous
#include <cuda_runtime.h>
#include <math.h>

#define NUM_EXPERTS 16
#define FREQ_BINS   2097152
#define ROW_V       (FREQ_BINS / 4)          // 524288 float4 per row = 2^19
#define TPB         256
#define ITERS       8
#define BLOCKS_X    (ROW_V / (TPB * ITERS))  // 256

__device__ int g_bounds[2 * NUM_EXPERTS];    // [start_e, end_e] pairs

// Prep: ONE warp, no shared memory, no block barrier.
// Lanes 0..14 compute double-precision sigmoids in parallel (XLA logistic
// = 0.5 + 0.5*tanh(0.5x), cast to f32 — byte-identical to every passing
// round, rel_err=0.0). Lane 0 gathers via shfl, sorts 17 values, writes the
// 16 [start,end) pairs, fences, and TRIGGERS the PDL dependency so the masks
// grid unparks before this kernel's teardown completes.
__global__ void prep_kernel(const float* __restrict__ bp) {
    const int lane = threadIdx.x;

    float my = 0.0f;
    if (lane < NUM_EXPERTS - 1) {
        double x = (double)bp[lane];
        my = (float)(0.5 + 0.5 * tanh(0.5 * x));
    }

    // Lane 0 gathers all 15 sigmoid results.
    float b[NUM_EXPERTS + 1];
    b[0] = 0.0f;
    b[NUM_EXPERTS] = 1.0f;
#pragma unroll
    for (int i = 0; i < NUM_EXPERTS - 1; i++)
        b[i + 1] = __shfl_sync(0xFFFFFFFFu, my, i);

    if (lane == 0) {
        for (int i = 1; i <= NUM_EXPERTS; i++) {   // insertion sort, 17 elems
            float key = b[i];
            int j = i - 1;
            while (j >= 0 && b[j] > key) { b[j + 1] = b[j]; j--; }
            b[j + 1] = key;
        }
#pragma unroll
        for (int e = 0; e < NUM_EXPERTS; e++) {
            g_bounds[2 * e]     = (int)(b[e] * 2097151.0f);   // f32 mul + trunc
            g_bounds[2 * e + 1] = (e < NUM_EXPERTS - 1)
                                    ? (int)(b[e + 1] * 2097151.0f)
                                    : FREQ_BINS;
        }
        __threadfence();
#if __CUDA_ARCH__ >= 900
        cudaTriggerProgrammaticLaunchCompletion();
#endif
    }
}

// Pure STG.128 write stream — unchanged from R3 (measured at the HBM write
// ceiling: 20.8us, 6.45 TB/s effective). blockIdx.y = expert row; in-range
// test is one unsigned compare per element.
__global__ void __launch_bounds__(TPB) masks_kernel(float4* __restrict__ out) {
#if __CUDA_ARCH__ >= 900
    cudaGridDependencySynchronize();
#endif
    const int e  = blockIdx.y;
    const int s  = g_bounds[2 * e];
    const unsigned len = (unsigned)(g_bounds[2 * e + 1] - s);

    float4* row = out + (size_t)e * ROW_V;
    const unsigned base = blockIdx.x * (TPB * ITERS) + threadIdx.x;

#pragma unroll
    for (int i = 0; i < ITERS; i++) {
        unsigned v = base + i * TPB;       // float4 index within the row
        int p = (int)(v << 2) - s;         // element offset relative to start
        float4 f;
        f.x = ((unsigned)(p    ) < len) ? 1.0f : 0.0f;
        f.y = ((unsigned)(p + 1) < len) ? 1.0f : 0.0f;
        f.z = ((unsigned)(p + 2) < len) ? 1.0f : 0.0f;
        f.w = ((unsigned)(p + 3) < len) ? 1.0f : 0.0f;
        row[v] = f;
    }
}

extern "C" void kernel_launch(void* const* d_in, const int* in_sizes, int n_in,
                              void* d_out, int out_size) {
    const float* bound_params = (const float*)d_in[0];
    float4* out = (float4*)d_out;

    prep_kernel<<<1, 32>>>(bound_params);

    // PDL: masks pre-launches and parks at cudaGridDependencySynchronize until
    // prep's explicit trigger (bounds written + fenced), not prep's teardown.
    cudaLaunchConfig_t cfg = {};
    cfg.gridDim  = dim3(BLOCKS_X, NUM_EXPERTS);
    cfg.blockDim = dim3(TPB);
    cudaLaunchAttribute attr[1];
    attr[0].id = cudaLaunchAttributeProgrammaticStreamSerialization;
    attr[0].val.programmaticStreamSerializationAllowed = 1;
    cfg.attrs    = attr;
    cfg.numAttrs = 1;
    cudaLaunchKernelEx(&cfg, masks_kernel, out);
}